// round 1
// baseline (speedup 1.0000x reference)
#include <cuda_runtime.h>
#include <math.h>
#include <stdint.h>

// ---------------------------------------------------------------------------
// YOLO loss, 3 levels. B=8, A=3, M=64 targets, 80 classes, grids 76/38/19.
// Node 1: prep   (1 block)   — target preprocessing + anchor matching
// Node 2: dense  (712 blocks)— no-object softplus with ignore mask
// Node 3: final  (1 block)   — positive pairs (CIoU/obj/cls) + reduction
// ---------------------------------------------------------------------------

#define NBATCH 8
#define MTGT   64
#define NANCH  3
#define NCLS   80
#define NCHAN  85

// grid sizes / per-level constants
__device__ __constant__ int   C_W[3]    = {76, 38, 19};
__device__ __constant__ float C_RED[3]  = {8.0f, 16.0f, 32.0f};
__device__ __constant__ float C_XYS[3]  = {1.2f, 1.1f, 1.05f};
// anchors / reduction (exact fp32)
__device__ __constant__ float C_AW[3][3] = {
    {1.5f, 2.375f, 5.0f},
    {2.25f, 4.75f, 4.5f},
    {4.4375f, 6.0f, 14.34375f}};
__device__ __constant__ float C_AH[3][3] = {
    {2.0f, 4.5f, 3.5f},
    {4.6875f, 3.4375f, 9.125f},
    {3.4375f, 7.59375f, 12.53125f}};

// dense launch geometry (cells = 8*3*w*w)
#define NCELL0 138624
#define NCELL1 34656
#define NCELL2 8664
#define NBLK0  542
#define NBLK1  136
#define NBLK2  34
#define NBLK_TOTAL (NBLK0 + NBLK1 + NBLK2)   // 712

// --- scratch (device globals; no allocation allowed) -----------------------
__device__ float4 g_tcorn[3 * MTGT];   // target corners in grid units (from center±wh/2)
__device__ float  g_tarea[3 * MTGT];   // wx*wy
__device__ float4 g_tcwh [3 * MTGT];   // cx, cy, wx, wy
__device__ int    g_tmeta[3 * MTGT];   // bid | ti<<4 | tj<<12 | matchbits<<20
__device__ double g_negpart[NBLK_TOTAL];

// ---------------------------------------------------------------------------
__device__ __forceinline__ float softplus_f(float x) {
    // logaddexp(x, 0) = max(x,0) + log1p(exp(-|x|))
    return fmaxf(x, 0.0f) + log1pf(expf(-fabsf(x)));
}

// ---------------------------------------------------------------------------
// Node 1: per-(level,target) preprocessing + anchor matching
// ---------------------------------------------------------------------------
__global__ void prep_kernel(const float* __restrict__ targets) {
    int tid = threadIdx.x;              // 0..191
    if (tid >= 3 * MTGT) return;
    int L = tid / MTGT;
    int t = tid % MTGT;

    float r  = C_RED[L];
    float x1 = targets[t * 5 + 0] / r;
    float y1 = targets[t * 5 + 1] / r;
    float x2 = targets[t * 5 + 2] / r;
    float y2 = targets[t * 5 + 3] / r;
    int bid  = (int)targets[t * 5 + 4];

    float wx = x2 - x1, wy = y2 - y1;
    float cx = (x1 + x2) * 0.5f, cy = (y1 + y2) * 0.5f;
    int ti = (int)cx, tj = (int)cy;
    float tarea = wx * wy;

    // anchor/target IoU (wh-only), exactly as reference (fp32 same op order)
    float iou[3];
    #pragma unroll
    for (int a = 0; a < 3; ++a) {
        float aw = C_AW[L][a], ah = C_AH[L][a];
        float inter = fminf(aw, wx) * fminf(ah, wy);
        iou[a] = inter / ((aw * ah + tarea) - inter);
    }
    int best = 0;
    if (iou[1] > iou[best]) best = 1;
    if (iou[2] > iou[best]) best = 2;
    int mb = 0;
    #pragma unroll
    for (int a = 0; a < 3; ++a)
        if (iou[a] > 0.213f || a == best) mb |= (1 << a);

    int idx = L * MTGT + t;
    // corners as reference computes them in the dense pass: center ± wh/2
    g_tcorn[idx] = make_float4(cx - wx * 0.5f, cy - wy * 0.5f,
                               cx + wx * 0.5f, cy + wy * 0.5f);
    g_tarea[idx] = tarea;
    g_tcwh[idx]  = make_float4(cx, cy, wx, wy);
    g_tmeta[idx] = bid | (ti << 4) | (tj << 12) | (mb << 20);
}

// ---------------------------------------------------------------------------
// Node 2: dense no-object loss. One thread per cell (b, a, y, x).
// ---------------------------------------------------------------------------
__global__ void __launch_bounds__(256) dense_kernel(
    const float* __restrict__ pred0,
    const float* __restrict__ pred1,
    const float* __restrict__ pred2) {

    // level selection by block
    int L, blk;
    if (blockIdx.x >= NBLK0 + NBLK1)      { L = 2; blk = blockIdx.x - (NBLK0 + NBLK1); }
    else if (blockIdx.x >= NBLK0)         { L = 1; blk = blockIdx.x - NBLK0; }
    else                                  { L = 0; blk = blockIdx.x; }

    const float* pred = (L == 0) ? pred0 : ((L == 1) ? pred1 : pred2);
    int w  = C_W[L];
    int hw = w * w;
    int ncell = 24 * hw;      // B*A*h*w
    float s = C_XYS[L];
    float half_sm1 = 0.5f * (s - 1.0f);

    // ---- shared: targets of this level compacted per batch-id -------------
    __shared__ float4 s_corn[MTGT];
    __shared__ float  s_area[MTGT];
    __shared__ int    s_key [MTGT];     // ti | tj<<8 | matchbits<<16
    __shared__ int    s_cnt[NBATCH], s_fill[NBATCH], s_off[NBATCH + 1];

    int tid = threadIdx.x;
    if (tid < NBATCH) { s_cnt[tid] = 0; s_fill[tid] = 0; }
    __syncthreads();
    if (tid < MTGT) {
        int m = g_tmeta[L * MTGT + tid];
        atomicAdd(&s_cnt[m & 15], 1);
    }
    __syncthreads();
    if (tid == 0) {
        int acc = 0;
        #pragma unroll
        for (int i = 0; i < NBATCH; ++i) { s_off[i] = acc; acc += s_cnt[i]; }
        s_off[NBATCH] = acc;
    }
    __syncthreads();
    if (tid < MTGT) {
        int gi = L * MTGT + tid;
        int m  = g_tmeta[gi];
        int b  = m & 15;
        int pos = s_off[b] + atomicAdd(&s_fill[b], 1);
        s_corn[pos] = g_tcorn[gi];
        s_area[pos] = g_tarea[gi];
        s_key [pos] = ((m >> 4) & 255) | (((m >> 12) & 255) << 8) | (((m >> 20) & 7) << 16);
    }
    __syncthreads();

    // ---- per-cell work -----------------------------------------------------
    float local = 0.0f;
    int idx = blk * 256 + tid;
    if (idx < ncell) {
        int x  = idx % w;
        int r1 = idx / w;
        int y  = r1 % w;
        int r2 = r1 / w;
        int a  = r2 % 3;
        int b  = r2 / 3;

        int base = ((b * 3 + a) * NCHAN) * hw + y * w + x;
        float p0 = pred[base];
        float p1 = pred[base + hw];
        float p2 = pred[base + 2 * hw];
        float p3 = pred[base + 3 * hw];
        float po = pred[base + 4 * hw];

        float bx = (1.0f / (1.0f + expf(-p0))) * s - half_sm1;
        float by = (1.0f / (1.0f + expf(-p1))) * s - half_sm1;
        float pw = expf(p2) * C_AW[L][a];
        float ph = expf(p3) * C_AH[L][a];

        float cxa = bx + (float)x;
        float cya = by + (float)y;
        float bx1 = cxa - 0.5f * pw, bx2 = cxa + 0.5f * pw;
        float by1 = cya - 0.5f * ph, by2 = cya + 0.5f * ph;
        float parea = pw * ph;

        bool zero = false;
        int mykey = x | (y << 8);
        int kend = s_off[b + 1];
        for (int k = s_off[b]; k < kend; ++k) {
            int kk = s_key[k];
            if (((kk & 0xFFFF) == mykey) && ((kk >> (16 + a)) & 1)) { zero = true; break; }
            float4 c  = s_corn[k];
            float ix = fminf(bx2, c.z) - fmaxf(bx1, c.x);
            float iy = fminf(by2, c.w) - fmaxf(by1, c.y);
            float inter = fmaxf(ix, 0.0f) * fmaxf(iy, 0.0f);
            float uni   = (parea + s_area[k] + 1e-16f) - inter;
            if (inter > 0.7f * uni) { zero = true; break; }
        }
        if (!zero) local = softplus_f(po);
    }

    // ---- block reduce (double) --------------------------------------------
    __shared__ double dred[256];
    dred[tid] = (double)local;
    __syncthreads();
    #pragma unroll
    for (int sft = 128; sft > 0; sft >>= 1) {
        if (tid < sft) dred[tid] += dred[tid + sft];
        __syncthreads();
    }
    if (tid == 0) g_negpart[blockIdx.x] = dred[0];
}

// ---------------------------------------------------------------------------
// CIoU (forward)
// ---------------------------------------------------------------------------
__device__ __forceinline__ float ciou_f(
    float cx1, float cy1, float w1, float h1,
    float cx2, float cy2, float w2, float h2) {
    float b1x1 = cx1 - 0.5f * w1, b1x2 = cx1 + 0.5f * w1;
    float b1y1 = cy1 - 0.5f * h1, b1y2 = cy1 + 0.5f * h1;
    float b2x1 = cx2 - 0.5f * w2, b2x2 = cx2 + 0.5f * w2;
    float b2y1 = cy2 - 0.5f * h2, b2y2 = cy2 + 0.5f * h2;
    float iw = fminf(b1x2, b2x2) - fmaxf(b1x1, b2x1);
    float ih = fminf(b1y2, b2y2) - fmaxf(b1y1, b2y1);
    float inter = fmaxf(iw, 0.0f) * fmaxf(ih, 0.0f);
    float uni = w1 * h1 + w2 * h2 + 1e-16f - inter;
    float iou = inter / uni;
    float cw = fmaxf(b1x2, b2x2) - fminf(b1x1, b2x1);
    float ch = fmaxf(b1y2, b2y2) - fminf(b1y1, b2y1);
    float c2 = cw * cw + ch * ch + 1e-16f;
    float rho2 = (cx1 - cx2) * (cx1 - cx2) + (cy1 - cy2) * (cy1 - cy2);
    float d = atanf(w2 / h2) - atanf(w1 / h1);
    float v = (float)(4.0 / (M_PI * M_PI)) * d * d;
    float alpha = v / ((1.0f - iou) + v + 1e-16f);
    return iou - (rho2 / c2 + v * alpha);
}

// ---------------------------------------------------------------------------
// Node 3: positives + final deterministic reduction. 576 threads, 1 block.
// thread -> (L, t, a) pair.  Also folds in the 712 dense partials.
// ---------------------------------------------------------------------------
__global__ void __launch_bounds__(576) final_kernel(
    const float* __restrict__ pred0,
    const float* __restrict__ pred1,
    const float* __restrict__ pred2,
    const int*   __restrict__ cats,
    float* __restrict__ out) {

    int tid = threadIdx.x;          // 0..575
    int L = tid / (MTGT * 3);
    int rem = tid % (MTGT * 3);
    int t = rem / 3;
    int a = rem % 3;

    double iou_s = 0.0, obj_s = 0.0, cls_s = 0.0, neg_s = 0.0;

    // pick up dense partials (deterministic: fixed mapping)
    neg_s = g_negpart[tid];
    if (tid + 576 < NBLK_TOTAL) neg_s += g_negpart[tid + 576];

    int gi = L * MTGT + t;
    int meta = g_tmeta[gi];
    if ((meta >> (20 + a)) & 1) {
        int bid = meta & 15;
        int ti  = (meta >> 4) & 255;
        int tj  = (meta >> 12) & 255;
        const float* pred = (L == 0) ? pred0 : ((L == 1) ? pred1 : pred2);
        int w = C_W[L];
        int hw = w * w;
        float s = C_XYS[L];
        float half_sm1 = 0.5f * (s - 1.0f);

        int base = ((bid * 3 + a) * NCHAN) * hw + tj * w + ti;
        float p0 = pred[base];
        float p1 = pred[base + hw];
        float p2 = pred[base + 2 * hw];
        float p3 = pred[base + 3 * hw];
        float po = pred[base + 4 * hw];

        float bx = (1.0f / (1.0f + expf(-p0))) * s - half_sm1;
        float by = (1.0f / (1.0f + expf(-p1))) * s - half_sm1;
        float pw = expf(p2) * C_AW[L][a];
        float ph = expf(p3) * C_AH[L][a];

        float4 cwh = g_tcwh[gi];
        float fx = cwh.x - (float)ti;
        float fy = cwh.y - (float)tj;

        float ciou = ciou_f(bx, by, pw, ph, fx, fy, cwh.z, cwh.w);
        iou_s = (double)(1.0f - ciou);
        obj_s = (double)(softplus_f(po) - po);

        int cat = cats[t] - 1;   // 0..79
        float cls_acc = 0.0f;
        #pragma unroll 4
        for (int c = 0; c < NCLS; ++c) {
            float xl = pred[base + (5 + c) * hw];
            float bce = softplus_f(xl);
            if (c == cat) bce -= xl;
            cls_acc += bce;
        }
        cls_s = (double)cls_acc;
    }

    // ---- block reductions (deterministic tree) -----------------------------
    __shared__ double sred[576];
    double totals[4];
    double vals[4] = {iou_s, obj_s, cls_s, neg_s};
    #pragma unroll
    for (int q = 0; q < 4; ++q) {
        sred[tid] = vals[q];
        __syncthreads();
        for (int sft = 512; sft > 0; sft >>= 1) {
            if (tid < sft && tid + sft < 576) sred[tid] += sred[tid + sft];
            __syncthreads();
        }
        totals[q] = sred[0];
        __syncthreads();
    }

    if (tid == 0) {
        out[0] = (float)(0.07 * totals[0]);             // COORD_SCALE * iou
        out[1] = (float)(totals[1] + totals[3]);        // obj_pos + obj_neg
        out[2] = (float)(totals[2]);                    // cls
    }
}

// ---------------------------------------------------------------------------
extern "C" void kernel_launch(void* const* d_in, const int* in_sizes, int n_in,
                              void* d_out, int out_size) {
    const float* pred0   = (const float*)d_in[0];
    const float* pred1   = (const float*)d_in[1];
    const float* pred2   = (const float*)d_in[2];
    const float* targets = (const float*)d_in[3];
    const int*   cats    = (const int*)  d_in[4];
    float* out = (float*)d_out;

    prep_kernel <<<1, 192>>>(targets);
    dense_kernel<<<NBLK_TOTAL, 256>>>(pred0, pred1, pred2);
    final_kernel<<<1, 576>>>(pred0, pred1, pred2, cats, out);
}

// round 2
// speedup vs baseline: 1.0060x; 1.0060x over previous
#include <cuda_runtime.h>
#include <math.h>
#include <stdint.h>

// ---------------------------------------------------------------------------
// YOLO loss, fused single kernel. B=8, A=3, M=64 targets, 80 classes.
// 712 blocks x 256 threads. Each block:
//   phase 1: recompute per-level target prep (cheap) into shared
//   phase 2: dense no-object loss for its 256 cells -> double partial
//   last block: positives (CIoU/obj/cls) + deterministic final reduction
// ---------------------------------------------------------------------------

#define NBATCH 8
#define MTGT   64
#define NCLS   80
#define NCHAN  85

__device__ __constant__ int   C_W[3]    = {76, 38, 19};
__device__ __constant__ float C_RED[3]  = {8.0f, 16.0f, 32.0f};
__device__ __constant__ float C_XYS[3]  = {1.2f, 1.1f, 1.05f};
__device__ __constant__ float C_AW[3][3] = {
    {1.5f, 2.375f, 5.0f},
    {2.25f, 4.75f, 4.5f},
    {4.4375f, 6.0f, 14.34375f}};
__device__ __constant__ float C_AH[3][3] = {
    {2.0f, 4.5f, 3.5f},
    {4.6875f, 3.4375f, 9.125f},
    {3.4375f, 7.59375f, 12.53125f}};

#define NBLK0  542
#define NBLK1  136
#define NBLK2  34
#define NBLK_TOTAL (NBLK0 + NBLK1 + NBLK2)   // 712

__device__ double   g_negpart[NBLK_TOTAL];
__device__ unsigned g_done = 0;

// ---------------------------------------------------------------------------
__device__ __forceinline__ float softplus_f(float x) {
    return fmaxf(x, 0.0f) + log1pf(expf(-fabsf(x)));
}

struct TPrep {
    float4 corn;   // x1,y1,x2,y2 (grid units, center +/- wh/2)
    float4 cwh;    // cx, cy, wx, wy
    float  area;
    int    meta;   // bid | ti<<4 | tj<<12 | matchbits<<20
};

// per-(level,target) preprocessing + anchor matching (exact fp32 order)
__device__ __forceinline__ TPrep prep_one(int L, int t,
                                          const float* __restrict__ targets) {
    float r  = C_RED[L];
    float x1 = targets[t * 5 + 0] / r;
    float y1 = targets[t * 5 + 1] / r;
    float x2 = targets[t * 5 + 2] / r;
    float y2 = targets[t * 5 + 3] / r;
    int bid  = (int)targets[t * 5 + 4];

    float wx = x2 - x1, wy = y2 - y1;
    float cx = (x1 + x2) * 0.5f, cy = (y1 + y2) * 0.5f;
    int ti = (int)cx, tj = (int)cy;
    float tarea = wx * wy;

    float iou[3];
    #pragma unroll
    for (int a = 0; a < 3; ++a) {
        float aw = C_AW[L][a], ah = C_AH[L][a];
        float inter = fminf(aw, wx) * fminf(ah, wy);
        iou[a] = inter / ((aw * ah + tarea) - inter);
    }
    int best = 0;
    if (iou[1] > iou[best]) best = 1;
    if (iou[2] > iou[best]) best = 2;
    int mb = 0;
    #pragma unroll
    for (int a = 0; a < 3; ++a)
        if (iou[a] > 0.213f || a == best) mb |= (1 << a);

    TPrep p;
    p.corn = make_float4(cx - wx * 0.5f, cy - wy * 0.5f,
                         cx + wx * 0.5f, cy + wy * 0.5f);
    p.cwh  = make_float4(cx, cy, wx, wy);
    p.area = tarea;
    p.meta = bid | (ti << 4) | (tj << 12) | (mb << 20);
    return p;
}

// CIoU (forward)
__device__ __forceinline__ float ciou_f(
    float cx1, float cy1, float w1, float h1,
    float cx2, float cy2, float w2, float h2) {
    float b1x1 = cx1 - 0.5f * w1, b1x2 = cx1 + 0.5f * w1;
    float b1y1 = cy1 - 0.5f * h1, b1y2 = cy1 + 0.5f * h1;
    float b2x1 = cx2 - 0.5f * w2, b2x2 = cx2 + 0.5f * w2;
    float b2y1 = cy2 - 0.5f * h2, b2y2 = cy2 + 0.5f * h2;
    float iw = fminf(b1x2, b2x2) - fmaxf(b1x1, b2x1);
    float ih = fminf(b1y2, b2y2) - fmaxf(b1y1, b2y1);
    float inter = fmaxf(iw, 0.0f) * fmaxf(ih, 0.0f);
    float uni = w1 * h1 + w2 * h2 + 1e-16f - inter;
    float iou = inter / uni;
    float cw = fmaxf(b1x2, b2x2) - fminf(b1x1, b2x1);
    float ch = fmaxf(b1y2, b2y2) - fminf(b1y1, b2y1);
    float c2 = cw * cw + ch * ch + 1e-16f;
    float rho2 = (cx1 - cx2) * (cx1 - cx2) + (cy1 - cy2) * (cy1 - cy2);
    float d = atanf(w2 / h2) - atanf(w1 / h1);
    float v = (float)(4.0 / (M_PI * M_PI)) * d * d;
    float alpha = v / ((1.0f - iou) + v + 1e-16f);
    return iou - (rho2 / c2 + v * alpha);
}

// ---------------------------------------------------------------------------
__global__ void __launch_bounds__(256) yolo_fused_kernel(
    const float* __restrict__ pred0,
    const float* __restrict__ pred1,
    const float* __restrict__ pred2,
    const float* __restrict__ targets,
    const int*   __restrict__ cats,
    float* __restrict__ out) {

    // ---- level decode ------------------------------------------------------
    int L, blk;
    if (blockIdx.x >= NBLK0 + NBLK1)      { L = 2; blk = blockIdx.x - (NBLK0 + NBLK1); }
    else if (blockIdx.x >= NBLK0)         { L = 1; blk = blockIdx.x - NBLK0; }
    else                                  { L = 0; blk = blockIdx.x; }

    const float* pred = (L == 0) ? pred0 : ((L == 1) ? pred1 : pred2);
    int w  = C_W[L];
    int hw = w * w;
    int ncell = 24 * hw;
    float s = C_XYS[L];
    float half_sm1 = 0.5f * (s - 1.0f);

    int tid  = threadIdx.x;
    int lane = tid & 31;
    int wid  = tid >> 5;

    // ---- phase 1: per-level prep, compacted per batch-id in shared --------
    __shared__ float4 s_corn[MTGT];
    __shared__ float  s_area[MTGT];
    __shared__ int    s_key [MTGT];   // ti | tj<<8 | matchbits<<16
    __shared__ int    s_cnt[NBATCH], s_fill[NBATCH], s_off[NBATCH + 1];

    TPrep myp;
    if (tid < NBATCH) { s_cnt[tid] = 0; s_fill[tid] = 0; }
    __syncthreads();
    if (tid < MTGT) {
        myp = prep_one(L, tid, targets);
        atomicAdd(&s_cnt[myp.meta & 15], 1);
    }
    __syncthreads();
    if (tid == 0) {
        int acc = 0;
        #pragma unroll
        for (int i = 0; i < NBATCH; ++i) { s_off[i] = acc; acc += s_cnt[i]; }
        s_off[NBATCH] = acc;
    }
    __syncthreads();
    if (tid < MTGT) {
        int b = myp.meta & 15;
        int pos = s_off[b] + atomicAdd(&s_fill[b], 1);
        s_corn[pos] = myp.corn;
        s_area[pos] = myp.area;
        s_key [pos] = ((myp.meta >> 4) & 255) | (((myp.meta >> 12) & 255) << 8)
                    | (((myp.meta >> 20) & 7) << 16);
    }
    __syncthreads();

    // ---- phase 2: dense no-object ------------------------------------------
    float local = 0.0f;
    int idx = blk * 256 + tid;
    if (idx < ncell) {
        int x  = idx % w;
        int r1 = idx / w;
        int y  = r1 % w;
        int r2 = r1 / w;
        int a  = r2 % 3;
        int b  = r2 / 3;

        int base = ((b * 3 + a) * NCHAN) * hw + y * w + x;
        float p0 = pred[base];
        float p1 = pred[base + hw];
        float p2 = pred[base + 2 * hw];
        float p3 = pred[base + 3 * hw];
        float po = pred[base + 4 * hw];

        float bx = (1.0f / (1.0f + expf(-p0))) * s - half_sm1;
        float by = (1.0f / (1.0f + expf(-p1))) * s - half_sm1;
        float pw = expf(p2) * C_AW[L][a];
        float ph = expf(p3) * C_AH[L][a];

        float cxa = bx + (float)x;
        float cya = by + (float)y;
        float bx1 = cxa - 0.5f * pw, bx2 = cxa + 0.5f * pw;
        float by1 = cya - 0.5f * ph, by2 = cya + 0.5f * ph;
        float parea = pw * ph;

        bool zero = false;
        int mykey = x | (y << 8);
        int kend = s_off[b + 1];
        for (int k = s_off[b]; k < kend; ++k) {
            int kk = s_key[k];
            if (((kk & 0xFFFF) == mykey) && ((kk >> (16 + a)) & 1)) { zero = true; break; }
            float4 c  = s_corn[k];
            float ix = fminf(bx2, c.z) - fmaxf(bx1, c.x);
            float iy = fminf(by2, c.w) - fmaxf(by1, c.y);
            float inter = fmaxf(ix, 0.0f) * fmaxf(iy, 0.0f);
            float uni   = (parea + s_area[k] + 1e-16f) - inter;
            if (inter > 0.7f * uni) { zero = true; break; }
        }
        if (!zero) local = softplus_f(po);
    }

    // ---- block reduce (double, deterministic) -------------------------------
    {
        double v = (double)local;
        #pragma unroll
        for (int o = 16; o > 0; o >>= 1)
            v += __shfl_down_sync(0xFFFFFFFFu, v, o);
        __shared__ double wsum[8];
        if (lane == 0) wsum[wid] = v;
        __syncthreads();
        if (tid == 0) {
            double t2 = 0.0;
            #pragma unroll
            for (int i = 0; i < 8; ++i) t2 += wsum[i];
            g_negpart[blockIdx.x] = t2;
        }
    }

    // ---- elect last block ----------------------------------------------------
    __shared__ int s_last;
    if (tid == 0) {
        __threadfence();
        unsigned old = atomicAdd(&g_done, 1u);
        s_last = (old == NBLK_TOTAL - 1) ? 1 : 0;
    }
    __syncthreads();
    if (!s_last) return;
    __threadfence();

    // =========================================================================
    // FINAL phase (last block only, 256 threads)
    // =========================================================================
    __shared__ int    f_meta[3 * MTGT];
    __shared__ float4 f_cwh [3 * MTGT];

    if (tid < 3 * MTGT) {
        int FL = tid / MTGT, ft = tid % MTGT;
        TPrep p = prep_one(FL, ft, targets);
        f_meta[tid] = p.meta;
        f_cwh [tid] = p.cwh;
    }
    __syncthreads();

    double iou_s = 0.0, obj_s = 0.0, cls_s = 0.0, neg_s = 0.0;

    // dense partials: fixed strided mapping per thread
    for (int i = tid; i < NBLK_TOTAL; i += 256)
        neg_s += g_negpart[i];

    // positives: 576 (L,t,a) pairs, threads handle tid, tid+256, tid+512
    for (int p = tid; p < 3 * MTGT * 3; p += 256) {
        int FL  = p / (MTGT * 3);
        int rem = p % (MTGT * 3);
        int t   = rem / 3;
        int a   = rem % 3;
        int gi  = FL * MTGT + t;
        int meta = f_meta[gi];
        if (!((meta >> (20 + a)) & 1)) continue;

        int bid = meta & 15;
        int ti  = (meta >> 4) & 255;
        int tj  = (meta >> 12) & 255;
        const float* fp = (FL == 0) ? pred0 : ((FL == 1) ? pred1 : pred2);
        int fw = C_W[FL];
        int fhw = fw * fw;
        float fs = C_XYS[FL];
        float fhs = 0.5f * (fs - 1.0f);

        int base = ((bid * 3 + a) * NCHAN) * fhw + tj * fw + ti;
        float p0 = fp[base];
        float p1 = fp[base + fhw];
        float p2 = fp[base + 2 * fhw];
        float p3 = fp[base + 3 * fhw];
        float po = fp[base + 4 * fhw];

        float bx = (1.0f / (1.0f + expf(-p0))) * fs - fhs;
        float by = (1.0f / (1.0f + expf(-p1))) * fs - fhs;
        float pw = expf(p2) * C_AW[FL][a];
        float ph = expf(p3) * C_AH[FL][a];

        float4 cwh = f_cwh[gi];
        float fx = cwh.x - (float)ti;
        float fy = cwh.y - (float)tj;

        float ciou = ciou_f(bx, by, pw, ph, fx, fy, cwh.z, cwh.w);
        iou_s += (double)(1.0f - ciou);
        obj_s += (double)(softplus_f(po) - po);

        int cat = cats[t] - 1;
        float cls_acc = 0.0f;
        #pragma unroll 4
        for (int c = 0; c < NCLS; ++c) {
            float xl = fp[base + (5 + c) * fhw];
            float bce = softplus_f(xl);
            if (c == cat) bce -= xl;
            cls_acc += bce;
        }
        cls_s += (double)cls_acc;
    }

    // ---- final deterministic reduction over 256 threads ----------------------
    __shared__ double fred[8][4];
    double vals[4] = {iou_s, obj_s, cls_s, neg_s};
    #pragma unroll
    for (int q = 0; q < 4; ++q) {
        double v = vals[q];
        #pragma unroll
        for (int o = 16; o > 0; o >>= 1)
            v += __shfl_down_sync(0xFFFFFFFFu, v, o);
        if (lane == 0) fred[wid][q] = v;
    }
    __syncthreads();
    if (tid == 0) {
        double tot[4] = {0.0, 0.0, 0.0, 0.0};
        #pragma unroll
        for (int i = 0; i < 8; ++i) {
            tot[0] += fred[i][0];
            tot[1] += fred[i][1];
            tot[2] += fred[i][2];
            tot[3] += fred[i][3];
        }
        out[0] = (float)(0.07 * tot[0]);        // COORD_SCALE * iou
        out[1] = (float)(tot[1] + tot[3]);      // obj_pos + obj_neg
        out[2] = (float)(tot[2]);               // cls
        g_done = 0;                              // reset for graph replay
    }
}

// ---------------------------------------------------------------------------
extern "C" void kernel_launch(void* const* d_in, const int* in_sizes, int n_in,
                              void* d_out, int out_size) {
    const float* pred0   = (const float*)d_in[0];
    const float* pred1   = (const float*)d_in[1];
    const float* pred2   = (const float*)d_in[2];
    const float* targets = (const float*)d_in[3];
    const int*   cats    = (const int*)  d_in[4];
    float* out = (float*)d_out;

    yolo_fused_kernel<<<NBLK_TOTAL, 256>>>(pred0, pred1, pred2, targets, cats, out);
}

// round 3
// speedup vs baseline: 1.6342x; 1.6245x over previous
#include <cuda_runtime.h>
#include <math.h>
#include <stdint.h>

// ---------------------------------------------------------------------------
// YOLO loss, fused single kernel with distributed positives + geometric
// prefilter for the ignore test. B=8, A=3, M=64 targets, 80 classes.
// ---------------------------------------------------------------------------

#define NBATCH 8
#define MTGT   64
#define NCLS   80
#define NCHAN  85
#define NPAIR  (3 * MTGT * 3)   // 576

__device__ __constant__ int   C_W[3]    = {76, 38, 19};
__device__ __constant__ float C_RED[3]  = {8.0f, 16.0f, 32.0f};
__device__ __constant__ float C_XYS[3]  = {1.2f, 1.1f, 1.05f};
__device__ __constant__ float C_AW[3][3] = {
    {1.5f, 2.375f, 5.0f},
    {2.25f, 4.75f, 4.5f},
    {4.4375f, 6.0f, 14.34375f}};
__device__ __constant__ float C_AH[3][3] = {
    {2.0f, 4.5f, 3.5f},
    {4.6875f, 3.4375f, 9.125f},
    {3.4375f, 7.59375f, 12.53125f}};

#define NBLK0  542
#define NBLK1  136
#define NBLK2  34
#define NBLK_TOTAL (NBLK0 + NBLK1 + NBLK2)   // 712

__device__ double   g_negpart[NBLK_TOTAL];
__device__ double   g_posiou[NPAIR];
__device__ double   g_posobj[NPAIR];
__device__ double   g_poscls[NPAIR];
__device__ unsigned g_done = 0;

// ---------------------------------------------------------------------------
// exact softplus (used where bit-level closeness matters little anyway, but
// cheap fast variant for the dense bulk)
__device__ __forceinline__ float softplus_fast(float x) {
    return fmaxf(x, 0.0f) + __logf(1.0f + __expf(-fabsf(x)));
}

struct TPrep {
    float4 corn;   // x1,y1,x2,y2 (grid units)
    float4 cwh;    // cx, cy, wx, wy
    float  area;
    int    meta;   // bid | ti<<4 | tj<<12 | matchbits<<20
};

// per-(level,target) preprocessing + anchor matching — EXACT fp32 (IEEE div),
// same op order as the reference; this determines the discrete match set.
__device__ __forceinline__ TPrep prep_one(int L, int t,
                                          const float* __restrict__ targets) {
    float r  = C_RED[L];
    float x1 = targets[t * 5 + 0] / r;
    float y1 = targets[t * 5 + 1] / r;
    float x2 = targets[t * 5 + 2] / r;
    float y2 = targets[t * 5 + 3] / r;
    int bid  = (int)targets[t * 5 + 4];

    float wx = x2 - x1, wy = y2 - y1;
    float cx = (x1 + x2) * 0.5f, cy = (y1 + y2) * 0.5f;
    int ti = (int)cx, tj = (int)cy;
    float tarea = wx * wy;

    float iou[3];
    #pragma unroll
    for (int a = 0; a < 3; ++a) {
        float aw = C_AW[L][a], ah = C_AH[L][a];
        float inter = fminf(aw, wx) * fminf(ah, wy);
        iou[a] = inter / ((aw * ah + tarea) - inter);
    }
    int best = 0;
    if (iou[1] > iou[best]) best = 1;
    if (iou[2] > iou[best]) best = 2;
    int mb = 0;
    #pragma unroll
    for (int a = 0; a < 3; ++a)
        if (iou[a] > 0.213f || a == best) mb |= (1 << a);

    TPrep p;
    p.corn = make_float4(cx - wx * 0.5f, cy - wy * 0.5f,
                         cx + wx * 0.5f, cy + wy * 0.5f);
    p.cwh  = make_float4(cx, cy, wx, wy);
    p.area = tarea;
    p.meta = bid | (ti << 4) | (tj << 12) | (mb << 20);
    return p;
}

// CIoU (forward)
__device__ __forceinline__ float ciou_f(
    float cx1, float cy1, float w1, float h1,
    float cx2, float cy2, float w2, float h2) {
    float b1x1 = cx1 - 0.5f * w1, b1x2 = cx1 + 0.5f * w1;
    float b1y1 = cy1 - 0.5f * h1, b1y2 = cy1 + 0.5f * h1;
    float b2x1 = cx2 - 0.5f * w2, b2x2 = cx2 + 0.5f * w2;
    float b2y1 = cy2 - 0.5f * h2, b2y2 = cy2 + 0.5f * h2;
    float iw = fminf(b1x2, b2x2) - fmaxf(b1x1, b2x1);
    float ih = fminf(b1y2, b2y2) - fmaxf(b1y1, b2y1);
    float inter = fmaxf(iw, 0.0f) * fmaxf(ih, 0.0f);
    float uni = w1 * h1 + w2 * h2 + 1e-16f - inter;
    float iou = inter / uni;
    float cw = fmaxf(b1x2, b2x2) - fminf(b1x1, b2x1);
    float ch = fmaxf(b1y2, b2y2) - fminf(b1y1, b2y1);
    float c2 = cw * cw + ch * ch + 1e-16f;
    float rho2 = (cx1 - cx2) * (cx1 - cx2) + (cy1 - cy2) * (cy1 - cy2);
    float d = atanf(w2 / h2) - atanf(w1 / h1);
    float v = (float)(4.0 / (M_PI * M_PI)) * d * d;
    float alpha = v / ((1.0f - iou) + v + 1e-16f);
    return iou - (rho2 / c2 + v * alpha);
}

// ---------------------------------------------------------------------------
__global__ void __launch_bounds__(256) yolo_fused_kernel(
    const float* __restrict__ pred0,
    const float* __restrict__ pred1,
    const float* __restrict__ pred2,
    const float* __restrict__ targets,
    const int*   __restrict__ cats,
    float* __restrict__ out) {

    // ---- level decode ------------------------------------------------------
    int L, blk;
    if (blockIdx.x >= NBLK0 + NBLK1)      { L = 2; blk = blockIdx.x - (NBLK0 + NBLK1); }
    else if (blockIdx.x >= NBLK0)         { L = 1; blk = blockIdx.x - NBLK0; }
    else                                  { L = 0; blk = blockIdx.x; }

    const float* pred = (L == 0) ? pred0 : ((L == 1) ? pred1 : pred2);
    int w  = C_W[L];
    int hw = w * w;
    int ncell = 24 * hw;
    float s = C_XYS[L];
    float half_sm1 = 0.5f * (s - 1.0f);

    int tid  = threadIdx.x;
    int lane = tid & 31;
    int wid  = tid >> 5;

    // ---- phase 1: per-level prep, compacted per batch-id in shared ---------
    __shared__ float4 s_corn[MTGT];
    __shared__ float  s_area[MTGT];
    __shared__ int    s_key [MTGT];   // ti | tj<<8 | matchbits<<16
    __shared__ int4   s_pf  [MTGT];   // xlo, dx, ylo, dy  (conservative cell bbox)
    __shared__ int    s_cnt[NBATCH], s_fill[NBATCH], s_off[NBATCH + 1];

    TPrep myp;
    if (tid < NBATCH) { s_cnt[tid] = 0; s_fill[tid] = 0; }
    __syncthreads();
    if (tid < MTGT) {
        myp = prep_one(L, tid, targets);
        atomicAdd(&s_cnt[myp.meta & 15], 1);
    }
    __syncthreads();
    if (tid == 0) {
        int acc = 0;
        #pragma unroll
        for (int i = 0; i < NBATCH; ++i) { s_off[i] = acc; acc += s_cnt[i]; }
        s_off[NBATCH] = acc;
    }
    __syncthreads();
    if (tid < MTGT) {
        int b = myp.meta & 15;
        int pos = s_off[b] + atomicAdd(&s_fill[b], 1);
        s_corn[pos] = myp.corn;
        s_area[pos] = myp.area;
        s_key [pos] = ((myp.meta >> 4) & 255) | (((myp.meta >> 12) & 255) << 8)
                    | (((myp.meta >> 20) & 7) << 16);
        // conservative prefilter bbox: IoU>0.7 forces pred center within
        // target +/- 0.32*dim and cell within center +/- 1.1; use 0.4*dim + 2.
        float tw = myp.cwh.z, th = myp.cwh.w;
        int xlo = (int)floorf(myp.corn.x - 0.4f * tw - 2.0f);
        int xhi = (int)ceilf (myp.corn.z + 0.4f * tw + 2.0f);
        int ylo = (int)floorf(myp.corn.y - 0.4f * th - 2.0f);
        int yhi = (int)ceilf (myp.corn.w + 0.4f * th + 2.0f);
        s_pf[pos] = make_int4(xlo, xhi - xlo, ylo, yhi - ylo);
    }
    __syncthreads();

    // ---- phase 2: dense no-object -------------------------------------------
    float local = 0.0f;
    int idx = blk * 256 + tid;
    if (idx < ncell) {
        int x  = idx % w;
        int r1 = idx / w;
        int y  = r1 % w;
        int r2 = r1 / w;
        int a  = r2 % 3;
        int b  = r2 / 3;

        int base = ((b * 3 + a) * NCHAN) * hw + y * w + x;
        float po = pred[base + 4 * hw];

        // quick reject: outside every target's conservative bbox -> neg cell
        int kbeg = s_off[b], kend = s_off[b + 1];
        bool cand = false;
        for (int k = kbeg; k < kend; ++k) {
            int4 pf = s_pf[k];
            if ((unsigned)(x - pf.x) <= (unsigned)pf.y &&
                (unsigned)(y - pf.z) <= (unsigned)pf.w) { cand = true; break; }
        }

        bool zero = false;
        if (cand) {
            float p0 = pred[base];
            float p1 = pred[base + hw];
            float p2 = pred[base + 2 * hw];
            float p3 = pred[base + 3 * hw];

            float bx = __fdividef(1.0f, 1.0f + __expf(-p0)) * s - half_sm1;
            float by = __fdividef(1.0f, 1.0f + __expf(-p1)) * s - half_sm1;
            float pw = __expf(p2) * C_AW[L][a];
            float ph = __expf(p3) * C_AH[L][a];

            float cxa = bx + (float)x;
            float cya = by + (float)y;
            float bx1 = cxa - 0.5f * pw, bx2 = cxa + 0.5f * pw;
            float by1 = cya - 0.5f * ph, by2 = cya + 0.5f * ph;
            float parea = pw * ph;

            int mykey = x | (y << 8);
            for (int k = kbeg; k < kend; ++k) {
                int kk = s_key[k];
                if (((kk & 0xFFFF) == mykey) && ((kk >> (16 + a)) & 1)) { zero = true; break; }
                float4 c  = s_corn[k];
                float ix = fminf(bx2, c.z) - fmaxf(bx1, c.x);
                float iy = fminf(by2, c.w) - fmaxf(by1, c.y);
                float inter = fmaxf(ix, 0.0f) * fmaxf(iy, 0.0f);
                float uni   = (parea + s_area[k] + 1e-16f) - inter;
                if (inter > 0.7f * uni) { zero = true; break; }
            }
        }
        if (!zero) local = softplus_fast(po);
    }

    // ---- block reduce (double, deterministic) --------------------------------
    {
        double v = (double)local;
        #pragma unroll
        for (int o = 16; o > 0; o >>= 1)
            v += __shfl_down_sync(0xFFFFFFFFu, v, o);
        __shared__ double wsum[8];
        if (lane == 0) wsum[wid] = v;
        __syncthreads();
        if (tid == 0) {
            double t2 = 0.0;
            #pragma unroll
            for (int i = 0; i < 8; ++i) t2 += wsum[i];
            g_negpart[blockIdx.x] = t2;
        }
    }

    // ---- phase 3: distributed positive pairs (blocks 0..575) -----------------
    if (blockIdx.x < NPAIR) {
        __shared__ int    sp_meta;
        __shared__ float4 sp_cwh;
        __shared__ float  sp_cls[NCLS];
        __shared__ float  sp_io[2];     // (1-ciou), obj_pos

        int p   = blockIdx.x;
        int FL  = p / (MTGT * 3);
        int rem = p % (MTGT * 3);
        int t   = rem / 3;
        int a   = rem % 3;

        if (tid == 0) {
            TPrep pp = prep_one(FL, t, targets);
            sp_meta = pp.meta;
            sp_cwh  = pp.cwh;
        }
        __syncthreads();

        int meta = sp_meta;
        bool matched = (meta >> (20 + a)) & 1;
        if (matched) {
            int bid = meta & 15;
            int ti  = (meta >> 4) & 255;
            int tj  = (meta >> 12) & 255;
            const float* fp = (FL == 0) ? pred0 : ((FL == 1) ? pred1 : pred2);
            int fw  = C_W[FL];
            int fhw = fw * fw;
            int base = ((bid * 3 + a) * NCHAN) * fhw + tj * fw + ti;

            if (tid < NCLS) {
                float xl  = fp[base + (5 + tid) * fhw];
                float bce = softplus_fast(xl);
                if (tid == cats[t] - 1) bce -= xl;
                sp_cls[tid] = bce;
            } else if (tid == NCLS) {
                float fs  = C_XYS[FL];
                float fhs = 0.5f * (fs - 1.0f);
                float p0 = fp[base];
                float p1 = fp[base + fhw];
                float p2 = fp[base + 2 * fhw];
                float p3 = fp[base + 3 * fhw];
                float po = fp[base + 4 * fhw];

                float bx = __fdividef(1.0f, 1.0f + __expf(-p0)) * fs - fhs;
                float by = __fdividef(1.0f, 1.0f + __expf(-p1)) * fs - fhs;
                float pw = __expf(p2) * C_AW[FL][a];
                float ph = __expf(p3) * C_AH[FL][a];

                float4 cwh = sp_cwh;
                float fx = cwh.x - (float)ti;
                float fy = cwh.y - (float)tj;
                sp_io[0] = 1.0f - ciou_f(bx, by, pw, ph, fx, fy, cwh.z, cwh.w);
                sp_io[1] = softplus_fast(po) - po;
            }
        }
        __syncthreads();
        if (tid == 0) {
            double cls = 0.0, iou = 0.0, obj = 0.0;
            if (matched) {
                float acc = 0.0f;
                #pragma unroll 8
                for (int c = 0; c < NCLS; ++c) acc += sp_cls[c];
                cls = (double)acc;
                iou = (double)sp_io[0];
                obj = (double)sp_io[1];
            }
            g_posiou[p] = iou;
            g_posobj[p] = obj;
            g_poscls[p] = cls;
        }
    }

    // ---- elect last block ------------------------------------------------------
    __shared__ int s_last;
    if (tid == 0) {
        __threadfence();
        unsigned old = atomicAdd(&g_done, 1u);
        s_last = (old == NBLK_TOTAL - 1) ? 1 : 0;
    }
    __syncthreads();
    if (!s_last) return;
    __threadfence();

    // ---- final reduction (last block) -------------------------------------------
    double iou_s = 0.0, obj_s = 0.0, cls_s = 0.0, neg_s = 0.0;
    for (int i = tid; i < NBLK_TOTAL; i += 256) neg_s += g_negpart[i];
    for (int i = tid; i < NPAIR; i += 256) {
        iou_s += g_posiou[i];
        obj_s += g_posobj[i];
        cls_s += g_poscls[i];
    }

    __shared__ double fred[8][4];
    double vals[4] = {iou_s, obj_s, cls_s, neg_s};
    #pragma unroll
    for (int q = 0; q < 4; ++q) {
        double v = vals[q];
        #pragma unroll
        for (int o = 16; o > 0; o >>= 1)
            v += __shfl_down_sync(0xFFFFFFFFu, v, o);
        if (lane == 0) fred[wid][q] = v;
    }
    __syncthreads();
    if (tid == 0) {
        double tot[4] = {0.0, 0.0, 0.0, 0.0};
        #pragma unroll
        for (int i = 0; i < 8; ++i) {
            tot[0] += fred[i][0];
            tot[1] += fred[i][1];
            tot[2] += fred[i][2];
            tot[3] += fred[i][3];
        }
        out[0] = (float)(0.07 * tot[0]);        // COORD_SCALE * iou
        out[1] = (float)(tot[1] + tot[3]);      // obj_pos + obj_neg
        out[2] = (float)(tot[2]);               // cls
        g_done = 0;                              // reset for graph replay
    }
}

// ---------------------------------------------------------------------------
extern "C" void kernel_launch(void* const* d_in, const int* in_sizes, int n_in,
                              void* d_out, int out_size) {
    const float* pred0   = (const float*)d_in[0];
    const float* pred1   = (const float*)d_in[1];
    const float* pred2   = (const float*)d_in[2];
    const float* targets = (const float*)d_in[3];
    const int*   cats    = (const int*)  d_in[4];
    float* out = (float*)d_out;

    yolo_fused_kernel<<<NBLK_TOTAL, 256>>>(pred0, pred1, pred2, targets, cats, out);
}